// round 15
// baseline (speedup 1.0000x reference)
#include <cuda_runtime.h>
#include <cuda_fp16.h>
#include <math.h>
#include <stdint.h>

#define HIDDEN        1024
#define N_HEAD_WORDS  20000
#define N_HEAD        20003
#define N_TAIL1       40000
#define N_TAIL2       140000
#define E1            512
#define E2            256
#define OUT_STRIDE    200000
#define M_ROWS        1024

#define M_TILE 128
#define N_TILE 128

// ---- scratch (__device__ globals; no allocations allowed) ----
__device__ __half g_hx[M_ROWS * HIDDEN];
__device__ __half g_hWhead[(size_t)N_HEAD * HIDDEN];
__device__ __half g_hWproj1[E1 * HIDDEN];
__device__ __half g_hWproj2[E2 * HIDDEN];
__device__ __half g_hWtail1[(size_t)N_TAIL1 * E1];
__device__ __half g_hWtail2[(size_t)N_TAIL2 * E2];
__device__ __half g_proj1[M_ROWS * E1];
__device__ __half g_proj2[M_ROWS * E2];
__device__ __half g_tlog1[(size_t)M_ROWS * N_TAIL1];
__device__ __half g_tlog2[(size_t)M_ROWS * N_TAIL2];
__device__ float  g_cluster[M_ROWS * 4];
__device__ float  g_sumexp1[M_ROWS];
__device__ float  g_sumexp2[M_ROWS];

static __device__ __forceinline__ uint32_t smem_u32(const void* p) {
    uint32_t a;
    asm("{ .reg .u64 t; cvta.to.shared.u64 t, %1; cvt.u32.u64 %0, t; }"
        : "=r"(a) : "l"(p));
    return a;
}
static __device__ __forceinline__ uint32_t pack_h2(float x, float y) {
    __half2 h = __floats2half2_rn(x, y);
    return *reinterpret_cast<uint32_t*>(&h);
}
static __device__ __forceinline__ void mma16816(float* d, const uint32_t* a,
                                                const uint32_t* b) {
    asm volatile(
        "mma.sync.aligned.m16n8k16.row.col.f32.f16.f16.f32 "
        "{%0,%1,%2,%3}, {%4,%5,%6,%7}, {%8,%9}, {%0,%1,%2,%3};"
        : "+f"(d[0]), "+f"(d[1]), "+f"(d[2]), "+f"(d[3])
        : "r"(a[0]), "r"(a[1]), "r"(a[2]), "r"(a[3]), "r"(b[0]), "r"(b[1]));
}
static __device__ __forceinline__ void ldmx4(uint32_t* r, uint32_t addr) {
    asm volatile("ldmatrix.sync.aligned.m8n8.x4.shared.b16 {%0,%1,%2,%3}, [%4];"
                 : "=r"(r[0]), "=r"(r[1]), "=r"(r[2]), "=r"(r[3]) : "r"(addr));
}
static __device__ __forceinline__ uint32_t swz(uint32_t byte) {
    return byte ^ ((byte >> 3) & 0x30);
}

#define CP_ASYNC16(dst, src, sz) \
    asm volatile("cp.async.cg.shared.global [%0], [%1], 16, %2;" \
                 :: "r"(dst), "l"(src), "r"(sz))
#define CP_COMMIT()  asm volatile("cp.async.commit_group;" ::: "memory")
template <int NN>
static __device__ __forceinline__ void cp_wait() {
    asm volatile("cp.async.wait_group %0;" :: "n"(NN) : "memory");
}

#define STAGE_BYTES 16384

__global__ void zero_sums_kernel() {
    int i = blockIdx.x * blockDim.x + threadIdx.x;
    if (i < M_ROWS) { g_sumexp1[i] = 0.0f; g_sumexp2[i] = 0.0f; }
}

// fp32 -> fp16 bulk convert; evict-first reads (weights are touch-once)
__global__ void cvt_kernel(const float4* __restrict__ src, uint4* __restrict__ dst,
                           int n8) {
    int i = blockIdx.x * blockDim.x + threadIdx.x;
    if (i < n8) {
        float4 a = __ldcs(src + 2 * i);
        float4 b = __ldcs(src + 2 * i + 1);
        dst[i] = make_uint4(pack_h2(a.x, a.y), pack_h2(a.z, a.w),
                            pack_h2(b.x, b.y), pack_h2(b.z, b.w));
    }
}

// ---------------------------------------------------------------------------
// C[M,N] = A[M,K]*B[N,K]^T. fp16 in, fp16 mma, fp32 accum. CTA tile 128x128.
// WARPS=8: 8 warps (4x2), warp tile 32x64  (short-K: projs/tails)
// WARPS=4: 4 warps (2x2), warp tile 64x64  (long-K head)
// NSTAGES-deep cp.async pipeline, (NSTAGES-1)-ahead prefetch.
// MODE 0: fp16 store; MODE 1: head split; MODE 2: fp16 logits + sum(exp)
// ---------------------------------------------------------------------------
template <int MODE, int WARPS, int NSTAGES>
__global__ __launch_bounds__(32 * WARPS, 2)
void tc_gemm(const __half* __restrict__ A, int lda,
             const __half* __restrict__ B, int ldb,
             int N, int K,
             void* __restrict__ Cv, long long ldc,
             float* __restrict__ sumexp)
{
    constexpr int MT    = (WARPS == 8) ? 2 : 4;    // 16-row m-subtiles per warp
    constexpr int M_SUB = MT * 16;                 // 32 or 64
    constexpr int NTHR  = 32 * WARPS;
    constexpr int PREF  = NSTAGES - 1;             // prefetch distance

    extern __shared__ __align__(1024) char tiles[];
    const uint32_t tbase = smem_u32(tiles);
    const int tid  = threadIdx.x;
    const int warp = tid >> 5, lane = tid & 31;
    const int wm = (WARPS == 8) ? (warp & 3) : (warp & 1);
    const int wn = (WARPS == 8) ? (warp >> 2) : (warp >> 1);

    const int bm = blockIdx.x * M_TILE;
    const int bn = blockIdx.y * N_TILE;
    const int NC = K >> 5;

    float acc[MT][8][4];
    #pragma unroll
    for (int mt = 0; mt < MT; mt++)
        #pragma unroll
        for (int nt = 0; nt < 8; nt++)
            #pragma unroll
            for (int i = 0; i < 4; i++) acc[mt][nt][i] = 0.0f;

    auto load_stage = [&](int s, int c) {
        const int k0 = c << 5;
        const uint32_t sbA = tbase + (uint32_t)s * STAGE_BYTES;
        const uint32_t sbB = sbA + 8192;
        #pragma unroll
        for (int j = 0; j < 512 / NTHR; j++) {
            int f = tid + NTHR * j;             // 0..511
            int row = f >> 2, c16 = f & 3;
            uint32_t off = swz((uint32_t)(row << 6) + (c16 << 4));
            const __half* as = A + (size_t)(bm + row) * lda + k0 + c16 * 8;
            CP_ASYNC16(sbA + off, as, 16);
            const __half* bs = B + (size_t)(bn + row) * ldb + k0 + c16 * 8;
            CP_ASYNC16(sbB + off, bs, (bn + row < N) ? 16 : 0);
        }
    };

    const uint32_t a_row_l = (uint32_t)((lane & 7) + ((lane >> 3) & 1) * 8);
    const uint32_t a_kb_l  = (uint32_t)((lane >> 4) << 4);
    const uint32_t b_row_l = (uint32_t)((lane & 7) + (lane >> 4) * 8);
    const uint32_t b_kb_l  = (uint32_t)(((lane >> 3) & 1) << 4);

    auto compute_chunk = [&](int s) {
        const uint32_t abase = tbase + (uint32_t)s * STAGE_BYTES;
        const uint32_t bbase = abase + 8192;
        #pragma unroll
        for (int k16 = 0; k16 < 2; k16++) {
            uint32_t af[MT][4];
            #pragma unroll
            for (int mt = 0; mt < MT; mt++) {
                uint32_t row = (uint32_t)(wm * M_SUB + mt * 16) + a_row_l;
                uint32_t byte = (row << 6) + (uint32_t)(k16 * 32) + a_kb_l;
                ldmx4(af[mt], abase + swz(byte));
            }
            uint32_t bf[8][2];
            #pragma unroll
            for (int p = 0; p < 4; p++) {
                uint32_t row = (uint32_t)(wn * 64 + p * 16) + b_row_l;
                uint32_t byte = (row << 6) + (uint32_t)(k16 * 32) + b_kb_l;
                uint32_t r[4];
                ldmx4(r, bbase + swz(byte));
                bf[2*p][0] = r[0]; bf[2*p][1] = r[1];
                bf[2*p+1][0] = r[2]; bf[2*p+1][1] = r[3];
            }
            #pragma unroll
            for (int mt = 0; mt < MT; mt++)
                #pragma unroll
                for (int nt = 0; nt < 8; nt++)
                    mma16816(acc[mt][nt], af[mt], bf[nt]);
        }
    };

    #pragma unroll
    for (int s = 0; s < PREF; s++) {
        if (s < NC) load_stage(s, s);
        CP_COMMIT();
    }

    for (int c = 0; c < NC; c++) {
        cp_wait<NSTAGES - 2>();
        __syncthreads();
        if (c + PREF < NC) load_stage((c + PREF) % NSTAGES, c + PREF);
        CP_COMMIT();                 // unconditional: keeps group==chunk mapping
        compute_chunk(c % NSTAGES);
    }

    // ---- epilogue ----
    const int g = lane >> 2, tq = lane & 3;
    const bool fullw = (bn + N_TILE <= N_HEAD_WORDS);
    const bool fullN = (bn + N_TILE <= N);
    float rs[MT][2];
    #pragma unroll
    for (int mt = 0; mt < MT; mt++) { rs[mt][0] = 0.f; rs[mt][1] = 0.f; }

    #pragma unroll
    for (int mt = 0; mt < MT; mt++) {
        const int r = bm + wm * M_SUB + mt * 16 + g;
        #pragma unroll
        for (int nt = 0; nt < 8; nt++) {
            float* d = acc[mt][nt];
            const int cc = bn + wn * 64 + nt * 8 + 2 * tq;
            if (MODE == 0) {
                __half* Ch = (__half*)Cv;
                *(__half2*)&Ch[(size_t)r * ldc + cc]       = __floats2half2_rn(d[0], d[1]);
                *(__half2*)&Ch[(size_t)(r + 8) * ldc + cc] = __floats2half2_rn(d[2], d[3]);
            } else if (MODE == 1) {
                float* C = (float*)Cv;
                if (fullw) {
                    __stcs((float2*)&C[(size_t)r * ldc + cc],       make_float2(d[0], d[1]));
                    __stcs((float2*)&C[(size_t)(r + 8) * ldc + cc], make_float2(d[2], d[3]));
                } else {
                    #pragma unroll
                    for (int i = 0; i < 4; i++) {
                        int rr = r + (i >> 1) * 8;
                        int n  = cc + (i & 1);
                        if (n < N_HEAD_WORDS)  C[(size_t)rr * ldc + n] = d[i];
                        else if (n < N_HEAD)   g_cluster[rr * 4 + (n - N_HEAD_WORDS)] = d[i];
                    }
                }
            } else {
                __half* S = (__half*)Cv;
                if (fullN) {
                    *(__half2*)&S[(size_t)r * ldc + cc]       = __floats2half2_rn(d[0], d[1]);
                    *(__half2*)&S[(size_t)(r + 8) * ldc + cc] = __floats2half2_rn(d[2], d[3]);
                    rs[mt][0] += __expf(d[0]) + __expf(d[1]);
                    rs[mt][1] += __expf(d[2]) + __expf(d[3]);
                } else {
                    #pragma unroll
                    for (int i = 0; i < 4; i++) {
                        int rr = r + (i >> 1) * 8;
                        int n  = cc + (i & 1);
                        if (n < N) {
                            S[(size_t)rr * ldc + n] = __float2half_rn(d[i]);
                            rs[mt][i >> 1] += __expf(d[i]);
                        }
                    }
                }
            }
        }
    }
    if (MODE == 2) {
        __syncthreads();
        float* rowsum = (float*)tiles;
        if (tid < M_TILE) rowsum[tid] = 0.0f;
        __syncthreads();
        #pragma unroll
        for (int mt = 0; mt < MT; mt++) {
            atomicAdd(&rowsum[wm * M_SUB + mt * 16 + g],     rs[mt][0]);
            atomicAdd(&rowsum[wm * M_SUB + mt * 16 + g + 8], rs[mt][1]);
        }
        __syncthreads();
        if (tid < M_TILE) atomicAdd(&sumexp[bm + tid], rowsum[tid]);
    }
}

// out[row, col_off + c] = (float)lg[row*n + c] + cluster[row][cl] - log(sumexp[row])
__global__ void fixup_kernel(float* __restrict__ out,
                             const __half* __restrict__ lg,
                             const float* __restrict__ sumexp,
                             int col_off, int ncols, int cl)
{
    int row = blockIdx.y;
    float add = g_cluster[row * 4 + cl] - logf(sumexp[row]);
    int i = blockIdx.x * blockDim.x + threadIdx.x;
    if (i * 8 < ncols) {
        const uint4 v = __ldcs((const uint4*)(lg + (size_t)row * ncols) + i);
        float* p = out + (size_t)row * OUT_STRIDE + col_off + i * 8;
        float2 a = __half22float2(*(const __half2*)&v.x);
        float2 b = __half22float2(*(const __half2*)&v.y);
        float2 c = __half22float2(*(const __half2*)&v.z);
        float2 d = __half22float2(*(const __half2*)&v.w);
        __stcs((float4*)p,     make_float4(a.x + add, a.y + add, b.x + add, b.y + add));
        __stcs((float4*)p + 1, make_float4(c.x + add, c.y + add, d.x + add, d.y + add));
    }
}

extern "C" void kernel_launch(void* const* d_in, const int* in_sizes, int n_in,
                              void* d_out, int out_size)
{
    const float* x       = (const float*)d_in[0];
    const float* W_head  = (const float*)d_in[1];
    const float* W_proj1 = (const float*)d_in[2];
    const float* W_tail1 = (const float*)d_in[3];
    const float* W_proj2 = (const float*)d_in[4];
    const float* W_tail2 = (const float*)d_in[5];
    float* out = (float*)d_out;

    __half *hx, *hWh, *hWp1, *hWp2, *hWt1, *hWt2, *proj1, *proj2, *tl1, *tl2;
    float *se1, *se2;
    cudaGetSymbolAddress((void**)&hx,    g_hx);
    cudaGetSymbolAddress((void**)&hWh,   g_hWhead);
    cudaGetSymbolAddress((void**)&hWp1,  g_hWproj1);
    cudaGetSymbolAddress((void**)&hWp2,  g_hWproj2);
    cudaGetSymbolAddress((void**)&hWt1,  g_hWtail1);
    cudaGetSymbolAddress((void**)&hWt2,  g_hWtail2);
    cudaGetSymbolAddress((void**)&proj1, g_proj1);
    cudaGetSymbolAddress((void**)&proj2, g_proj2);
    cudaGetSymbolAddress((void**)&tl1,   g_tlog1);
    cudaGetSymbolAddress((void**)&tl2,   g_tlog2);
    cudaGetSymbolAddress((void**)&se1,   g_sumexp1);
    cudaGetSymbolAddress((void**)&se2,   g_sumexp2);

    const int SM_HEAD = 4 * STAGE_BYTES;   // 64 KB
    const int SM_TAIL = 6 * STAGE_BYTES;   // 96 KB (x2 CTAs = 192 <= 228)
    cudaFuncSetAttribute((void*)tc_gemm<0, 8, 6>, cudaFuncAttributeMaxDynamicSharedMemorySize, SM_TAIL);
    cudaFuncSetAttribute((void*)tc_gemm<1, 4, 4>, cudaFuncAttributeMaxDynamicSharedMemorySize, SM_HEAD);
    cudaFuncSetAttribute((void*)tc_gemm<2, 8, 6>, cudaFuncAttributeMaxDynamicSharedMemorySize, SM_TAIL);

    auto cvt_on = [&](cudaStream_t st, const float* s, __half* d, size_t n) {
        int n8 = (int)(n / 8);
        cvt_kernel<<<(n8 + 255) / 256, 256, 0, st>>>((const float4*)s, (uint4*)d, n8);
    };

    // ---- multi-stream fork/join: exactly 3 created streams (alloc-guard limit) ----
    cudaStream_t sA, sB, sC;
    cudaStreamCreateWithFlags(&sA, cudaStreamNonBlocking);
    cudaStreamCreateWithFlags(&sB, cudaStreamNonBlocking);
    cudaStreamCreateWithFlags(&sC, cudaStreamNonBlocking);
    cudaEvent_t evRoot, evHead, evWt1, evWt2, evF1, evF2;
    cudaEventCreateWithFlags(&evRoot, cudaEventDisableTiming);
    cudaEventCreateWithFlags(&evHead, cudaEventDisableTiming);
    cudaEventCreateWithFlags(&evWt1,  cudaEventDisableTiming);
    cudaEventCreateWithFlags(&evWt2,  cudaEventDisableTiming);
    cudaEventCreateWithFlags(&evF1,   cudaEventDisableTiming);
    cudaEventCreateWithFlags(&evF2,   cudaEventDisableTiming);

    zero_sums_kernel<<<4, 256>>>();
    cvt_on(0, x, hx, (size_t)M_ROWS * HIDDEN);
    cudaEventRecord(evRoot, 0);

    // tail-weight conversions on the otherwise-idle caller stream
    cvt_on(0, W_tail1, hWt1, (size_t)N_TAIL1 * E1);
    cudaEventRecord(evWt1, 0);
    cvt_on(0, W_tail2, hWt2, (size_t)N_TAIL2 * E2);
    cudaEventRecord(evWt2, 0);

    // chain A: head (4-warp, 4-stage, K=1024)
    cudaStreamWaitEvent(sA, evRoot, 0);
    cvt_on(sA, W_head, hWh, (size_t)N_HEAD * HIDDEN);
    tc_gemm<1, 4, 4><<<dim3(8, (N_HEAD + 127) / 128), 128, SM_HEAD, sA>>>(
        hx, HIDDEN, hWh, HIDDEN, N_HEAD, HIDDEN, out, OUT_STRIDE, nullptr);
    cudaEventRecord(evHead, sA);

    // chain B: proj1 -> tail1 (8-warp, 6-stage)
    cudaStreamWaitEvent(sB, evRoot, 0);
    cvt_on(sB, W_proj1, hWp1, (size_t)E1 * HIDDEN);
    tc_gemm<0, 8, 6><<<dim3(8, E1 / 128), 256, SM_TAIL, sB>>>(
        hx, HIDDEN, hWp1, HIDDEN, E1, HIDDEN, proj1, E1, nullptr);
    cudaStreamWaitEvent(sB, evWt1, 0);
    tc_gemm<2, 8, 6><<<dim3(8, (N_TAIL1 + 127) / 128), 256, SM_TAIL, sB>>>(
        proj1, E1, hWt1, E1, N_TAIL1, E1, tl1, N_TAIL1, se1);

    // chain C: proj2 -> tail2 (8-warp, 6-stage)
    cudaStreamWaitEvent(sC, evRoot, 0);
    cvt_on(sC, W_proj2, hWp2, (size_t)E2 * HIDDEN);
    tc_gemm<0, 8, 6><<<dim3(8, E2 / 128), 256, SM_TAIL, sC>>>(
        hx, HIDDEN, hWp2, HIDDEN, E2, HIDDEN, proj2, E2, nullptr);
    cudaStreamWaitEvent(sC, evWt2, 0);
    tc_gemm<2, 8, 6><<<dim3(8, (N_TAIL2 + 127) / 128), 256, SM_TAIL, sC>>>(
        proj2, E2, hWt2, E2, N_TAIL2, E2, tl2, N_TAIL2, se2);

    // fixups (need head's cluster logits + own tail's sumexp/logits)
    cudaStreamWaitEvent(sB, evHead, 0);
    fixup_kernel<<<dim3((N_TAIL1 / 8 + 255) / 256, M_ROWS), 256, 0, sB>>>(
        out, tl1, se1, 20000, N_TAIL1, 0);
    cudaEventRecord(evF1, sB);

    cudaStreamWaitEvent(sC, evHead, 0);
    fixup_kernel<<<dim3((N_TAIL2 / 8 + 255) / 256, M_ROWS), 256, 0, sC>>>(
        out, tl2, se2, 60000, N_TAIL2, 1);
    cudaEventRecord(evF2, sC);

    cudaStreamWaitEvent(0, evF1, 0);
    cudaStreamWaitEvent(0, evF2, 0);

    cudaEventDestroy(evRoot);
    cudaEventDestroy(evHead);
    cudaEventDestroy(evWt1);
    cudaEventDestroy(evWt2);
    cudaEventDestroy(evF1);
    cudaEventDestroy(evF2);
    cudaStreamDestroy(sA);
    cudaStreamDestroy(sB);
    cudaStreamDestroy(sC);
}

// round 17
// speedup vs baseline: 1.0419x; 1.0419x over previous
#include <cuda_runtime.h>
#include <cuda_fp16.h>
#include <math.h>
#include <stdint.h>

#define HIDDEN        1024
#define N_HEAD_WORDS  20000
#define N_HEAD        20003
#define N_TAIL1       40000
#define N_TAIL2       140000
#define E1            512
#define E2            256
#define OUT_STRIDE    200000
#define M_ROWS        1024

#define M_TILE 128
#define N_TILE 128
#define STAGES 4

// ---- scratch (__device__ globals; no allocations allowed) ----
__device__ __half g_hx[M_ROWS * HIDDEN];
__device__ __half g_hWhead[(size_t)N_HEAD * HIDDEN];
__device__ __half g_hWproj1[E1 * HIDDEN];
__device__ __half g_hWproj2[E2 * HIDDEN];
__device__ __half g_hWtail1[(size_t)N_TAIL1 * E1];
__device__ __half g_hWtail2[(size_t)N_TAIL2 * E2];
__device__ __half g_proj1[M_ROWS * E1];
__device__ __half g_proj2[M_ROWS * E2];
__device__ __half g_tlog1[(size_t)M_ROWS * N_TAIL1];
__device__ __half g_tlog2[(size_t)M_ROWS * N_TAIL2];
__device__ float  g_cluster[M_ROWS * 4];
__device__ float  g_sumexp1[M_ROWS];
__device__ float  g_sumexp2[M_ROWS];

static __device__ __forceinline__ uint32_t smem_u32(const void* p) {
    uint32_t a;
    asm("{ .reg .u64 t; cvta.to.shared.u64 t, %1; cvt.u32.u64 %0, t; }"
        : "=r"(a) : "l"(p));
    return a;
}
static __device__ __forceinline__ uint32_t pack_h2(float x, float y) {
    __half2 h = __floats2half2_rn(x, y);
    return *reinterpret_cast<uint32_t*>(&h);
}
static __device__ __forceinline__ void mma16816(float* d, const uint32_t* a,
                                                const uint32_t* b) {
    asm volatile(
        "mma.sync.aligned.m16n8k16.row.col.f32.f16.f16.f32 "
        "{%0,%1,%2,%3}, {%4,%5,%6,%7}, {%8,%9}, {%0,%1,%2,%3};"
        : "+f"(d[0]), "+f"(d[1]), "+f"(d[2]), "+f"(d[3])
        : "r"(a[0]), "r"(a[1]), "r"(a[2]), "r"(a[3]), "r"(b[0]), "r"(b[1]));
}
static __device__ __forceinline__ void ldmx4(uint32_t* r, uint32_t addr) {
    asm volatile("ldmatrix.sync.aligned.m8n8.x4.shared.b16 {%0,%1,%2,%3}, [%4];"
                 : "=r"(r[0]), "=r"(r[1]), "=r"(r[2]), "=r"(r[3]) : "r"(addr));
}
static __device__ __forceinline__ uint32_t swz(uint32_t byte) {
    return byte ^ ((byte >> 3) & 0x30);
}

#define CP_ASYNC16(dst, src, sz) \
    asm volatile("cp.async.cg.shared.global [%0], [%1], 16, %2;" \
                 :: "r"(dst), "l"(src), "r"(sz))
#define CP_COMMIT()  asm volatile("cp.async.commit_group;" ::: "memory")
#define CP_WAIT2()   asm volatile("cp.async.wait_group 2;" ::: "memory")

#define STAGE_BYTES 16384
#define SMEM_BYTES  (STAGES * STAGE_BYTES)

__global__ void zero_sums_kernel() {
    int i = blockIdx.x * blockDim.x + threadIdx.x;
    if (i < M_ROWS) { g_sumexp1[i] = 0.0f; g_sumexp2[i] = 0.0f; }
}

// fp32 -> fp16 bulk convert; evict-first reads (weights are touch-once)
__global__ void cvt_kernel(const float4* __restrict__ src, uint4* __restrict__ dst,
                           int n8) {
    int i = blockIdx.x * blockDim.x + threadIdx.x;
    if (i < n8) {
        float4 a = __ldcs(src + 2 * i);
        float4 b = __ldcs(src + 2 * i + 1);
        dst[i] = make_uint4(pack_h2(a.x, a.y), pack_h2(a.z, a.w),
                            pack_h2(b.x, b.y), pack_h2(b.z, b.w));
    }
}

// ---------------------------------------------------------------------------
// C[M,N] = A[M,K]*B[N,K]^T. fp16 in, fp16 mma, fp32 accum. CTA tile 128x128.
// WARPS=8: 8 warps (4x2), warp tile 32x64  (short-K kernels: projs/tails)
// WARPS=4: 4 warps (2x2), warp tile 64x64  (long-K head)
// 4-stage cp.async pipeline (measured best; 6-stage regressed).
// MODE 0: fp16 store; MODE 1: head split; MODE 2: fp16 logits (.cs) + sum(exp)
// ---------------------------------------------------------------------------
template <int MODE, int WARPS>
__global__ __launch_bounds__(32 * WARPS, 2)
void tc_gemm(const __half* __restrict__ A, int lda,
             const __half* __restrict__ B, int ldb,
             int N, int K,
             void* __restrict__ Cv, long long ldc,
             float* __restrict__ sumexp)
{
    constexpr int MT    = (WARPS == 8) ? 2 : 4;    // 16-row m-subtiles per warp
    constexpr int M_SUB = MT * 16;                 // 32 or 64
    constexpr int NTHR  = 32 * WARPS;

    extern __shared__ __align__(1024) char tiles[];
    const uint32_t tbase = smem_u32(tiles);
    const int tid  = threadIdx.x;
    const int warp = tid >> 5, lane = tid & 31;
    const int wm = (WARPS == 8) ? (warp & 3) : (warp & 1);
    const int wn = (WARPS == 8) ? (warp >> 2) : (warp >> 1);

    const int bm = blockIdx.x * M_TILE;
    const int bn = blockIdx.y * N_TILE;
    const int NC = K >> 5;

    float acc[MT][8][4];
    #pragma unroll
    for (int mt = 0; mt < MT; mt++)
        #pragma unroll
        for (int nt = 0; nt < 8; nt++)
            #pragma unroll
            for (int i = 0; i < 4; i++) acc[mt][nt][i] = 0.0f;

    auto load_stage = [&](int s, int c) {
        const int k0 = c << 5;
        const uint32_t sbA = tbase + (uint32_t)s * STAGE_BYTES;
        const uint32_t sbB = sbA + 8192;
        #pragma unroll
        for (int j = 0; j < 512 / NTHR; j++) {
            int f = tid + NTHR * j;             // 0..511
            int row = f >> 2, c16 = f & 3;
            uint32_t off = swz((uint32_t)(row << 6) + (c16 << 4));
            const __half* as = A + (size_t)(bm + row) * lda + k0 + c16 * 8;
            CP_ASYNC16(sbA + off, as, 16);
            const __half* bs = B + (size_t)(bn + row) * ldb + k0 + c16 * 8;
            CP_ASYNC16(sbB + off, bs, (bn + row < N) ? 16 : 0);
        }
    };

    const uint32_t a_row_l = (uint32_t)((lane & 7) + ((lane >> 3) & 1) * 8);
    const uint32_t a_kb_l  = (uint32_t)((lane >> 4) << 4);
    const uint32_t b_row_l = (uint32_t)((lane & 7) + (lane >> 4) * 8);
    const uint32_t b_kb_l  = (uint32_t)(((lane >> 3) & 1) << 4);

    auto compute_chunk = [&](int s) {
        const uint32_t abase = tbase + (uint32_t)s * STAGE_BYTES;
        const uint32_t bbase = abase + 8192;
        #pragma unroll
        for (int k16 = 0; k16 < 2; k16++) {
            uint32_t af[MT][4];
            #pragma unroll
            for (int mt = 0; mt < MT; mt++) {
                uint32_t row = (uint32_t)(wm * M_SUB + mt * 16) + a_row_l;
                uint32_t byte = (row << 6) + (uint32_t)(k16 * 32) + a_kb_l;
                ldmx4(af[mt], abase + swz(byte));
            }
            uint32_t bf[8][2];
            #pragma unroll
            for (int p = 0; p < 4; p++) {
                uint32_t row = (uint32_t)(wn * 64 + p * 16) + b_row_l;
                uint32_t byte = (row << 6) + (uint32_t)(k16 * 32) + b_kb_l;
                uint32_t r[4];
                ldmx4(r, bbase + swz(byte));
                bf[2*p][0] = r[0]; bf[2*p][1] = r[1];
                bf[2*p+1][0] = r[2]; bf[2*p+1][1] = r[3];
            }
            #pragma unroll
            for (int mt = 0; mt < MT; mt++)
                #pragma unroll
                for (int nt = 0; nt < 8; nt++)
                    mma16816(acc[mt][nt], af[mt], bf[nt]);
        }
    };

    #pragma unroll
    for (int s = 0; s < 3; s++) { load_stage(s, s); CP_COMMIT(); }

    for (int c = 0; c < NC; c++) {
        CP_WAIT2();
        __syncthreads();
        if (c + 3 < NC) load_stage((c + 3) & 3, c + 3);
        CP_COMMIT();                 // unconditional: keeps group==chunk mapping
        compute_chunk(c & 3);
    }

    // ---- epilogue ----
    const int g = lane >> 2, tq = lane & 3;
    const bool fullw = (bn + N_TILE <= N_HEAD_WORDS);
    const bool fullN = (bn + N_TILE <= N);
    float rs[MT][2];
    #pragma unroll
    for (int mt = 0; mt < MT; mt++) { rs[mt][0] = 0.f; rs[mt][1] = 0.f; }

    #pragma unroll
    for (int mt = 0; mt < MT; mt++) {
        const int r = bm + wm * M_SUB + mt * 16 + g;
        #pragma unroll
        for (int nt = 0; nt < 8; nt++) {
            float* d = acc[mt][nt];
            const int cc = bn + wn * 64 + nt * 8 + 2 * tq;
            if (MODE == 0) {
                __half* Ch = (__half*)Cv;
                *(__half2*)&Ch[(size_t)r * ldc + cc]       = __floats2half2_rn(d[0], d[1]);
                *(__half2*)&Ch[(size_t)(r + 8) * ldc + cc] = __floats2half2_rn(d[2], d[3]);
            } else if (MODE == 1) {
                float* C = (float*)Cv;
                if (fullw) {
                    __stcs((float2*)&C[(size_t)r * ldc + cc],       make_float2(d[0], d[1]));
                    __stcs((float2*)&C[(size_t)(r + 8) * ldc + cc], make_float2(d[2], d[3]));
                } else {
                    #pragma unroll
                    for (int i = 0; i < 4; i++) {
                        int rr = r + (i >> 1) * 8;
                        int n  = cc + (i & 1);
                        if (n < N_HEAD_WORDS)  C[(size_t)rr * ldc + n] = d[i];
                        else if (n < N_HEAD)   g_cluster[rr * 4 + (n - N_HEAD_WORDS)] = d[i];
                    }
                }
            } else {
                __half* S = (__half*)Cv;
                if (fullN) {
                    // evict-first: logits are dead until the fixup pass; keep
                    // W_tail tiles resident in L2 instead.
                    __stcs((unsigned int*)&S[(size_t)r * ldc + cc],
                           pack_h2(d[0], d[1]));
                    __stcs((unsigned int*)&S[(size_t)(r + 8) * ldc + cc],
                           pack_h2(d[2], d[3]));
                    rs[mt][0] += __expf(d[0]) + __expf(d[1]);
                    rs[mt][1] += __expf(d[2]) + __expf(d[3]);
                } else {
                    #pragma unroll
                    for (int i = 0; i < 4; i++) {
                        int rr = r + (i >> 1) * 8;
                        int n  = cc + (i & 1);
                        if (n < N) {
                            S[(size_t)rr * ldc + n] = __float2half_rn(d[i]);
                            rs[mt][i >> 1] += __expf(d[i]);
                        }
                    }
                }
            }
        }
    }
    if (MODE == 2) {
        __syncthreads();
        float* rowsum = (float*)tiles;
        if (tid < M_TILE) rowsum[tid] = 0.0f;
        __syncthreads();
        #pragma unroll
        for (int mt = 0; mt < MT; mt++) {
            atomicAdd(&rowsum[wm * M_SUB + mt * 16 + g],     rs[mt][0]);
            atomicAdd(&rowsum[wm * M_SUB + mt * 16 + g + 8], rs[mt][1]);
        }
        __syncthreads();
        if (tid < M_TILE) atomicAdd(&sumexp[bm + tid], rowsum[tid]);
    }
}

// out[row, col_off + c] = (float)lg[row*n + c] + cluster[row][cl] - log(sumexp[row])
__global__ void fixup_kernel(float* __restrict__ out,
                             const __half* __restrict__ lg,
                             const float* __restrict__ sumexp,
                             int col_off, int ncols, int cl)
{
    int row = blockIdx.y;
    float add = g_cluster[row * 4 + cl] - logf(sumexp[row]);
    int i = blockIdx.x * blockDim.x + threadIdx.x;
    if (i * 8 < ncols) {
        const uint4 v = __ldcs((const uint4*)(lg + (size_t)row * ncols) + i);
        float* p = out + (size_t)row * OUT_STRIDE + col_off + i * 8;
        float2 a = __half22float2(*(const __half2*)&v.x);
        float2 b = __half22float2(*(const __half2*)&v.y);
        float2 c = __half22float2(*(const __half2*)&v.z);
        float2 d = __half22float2(*(const __half2*)&v.w);
        __stcs((float4*)p,     make_float4(a.x + add, a.y + add, b.x + add, b.y + add));
        __stcs((float4*)p + 1, make_float4(c.x + add, c.y + add, d.x + add, d.y + add));
    }
}

extern "C" void kernel_launch(void* const* d_in, const int* in_sizes, int n_in,
                              void* d_out, int out_size)
{
    const float* x       = (const float*)d_in[0];
    const float* W_head  = (const float*)d_in[1];
    const float* W_proj1 = (const float*)d_in[2];
    const float* W_tail1 = (const float*)d_in[3];
    const float* W_proj2 = (const float*)d_in[4];
    const float* W_tail2 = (const float*)d_in[5];
    float* out = (float*)d_out;

    __half *hx, *hWh, *hWp1, *hWp2, *hWt1, *hWt2, *proj1, *proj2, *tl1, *tl2;
    float *se1, *se2;
    cudaGetSymbolAddress((void**)&hx,    g_hx);
    cudaGetSymbolAddress((void**)&hWh,   g_hWhead);
    cudaGetSymbolAddress((void**)&hWp1,  g_hWproj1);
    cudaGetSymbolAddress((void**)&hWp2,  g_hWproj2);
    cudaGetSymbolAddress((void**)&hWt1,  g_hWtail1);
    cudaGetSymbolAddress((void**)&hWt2,  g_hWtail2);
    cudaGetSymbolAddress((void**)&proj1, g_proj1);
    cudaGetSymbolAddress((void**)&proj2, g_proj2);
    cudaGetSymbolAddress((void**)&tl1,   g_tlog1);
    cudaGetSymbolAddress((void**)&tl2,   g_tlog2);
    cudaGetSymbolAddress((void**)&se1,   g_sumexp1);
    cudaGetSymbolAddress((void**)&se2,   g_sumexp2);

    cudaFuncSetAttribute((void*)tc_gemm<0, 8>, cudaFuncAttributeMaxDynamicSharedMemorySize, SMEM_BYTES);
    cudaFuncSetAttribute((void*)tc_gemm<1, 4>, cudaFuncAttributeMaxDynamicSharedMemorySize, SMEM_BYTES);
    cudaFuncSetAttribute((void*)tc_gemm<2, 8>, cudaFuncAttributeMaxDynamicSharedMemorySize, SMEM_BYTES);

    auto cvt_on = [&](cudaStream_t st, const float* s, __half* d, size_t n) {
        int n8 = (int)(n / 8);
        cvt_kernel<<<(n8 + 255) / 256, 256, 0, st>>>((const float4*)s, (uint4*)d, n8);
    };

    // ---- multi-stream fork/join: exactly 3 created streams (alloc-guard limit) ----
    cudaStream_t sA, sB, sC;
    cudaStreamCreateWithFlags(&sA, cudaStreamNonBlocking);
    cudaStreamCreateWithFlags(&sB, cudaStreamNonBlocking);
    cudaStreamCreateWithFlags(&sC, cudaStreamNonBlocking);
    cudaEvent_t evRoot, evHead, evWt1, evWt2, evF1, evF2;
    cudaEventCreateWithFlags(&evRoot, cudaEventDisableTiming);
    cudaEventCreateWithFlags(&evHead, cudaEventDisableTiming);
    cudaEventCreateWithFlags(&evWt1,  cudaEventDisableTiming);
    cudaEventCreateWithFlags(&evWt2,  cudaEventDisableTiming);
    cudaEventCreateWithFlags(&evF1,   cudaEventDisableTiming);
    cudaEventCreateWithFlags(&evF2,   cudaEventDisableTiming);

    zero_sums_kernel<<<4, 256>>>();
    cvt_on(0, x, hx, (size_t)M_ROWS * HIDDEN);
    cudaEventRecord(evRoot, 0);

    // tail-weight conversions on the otherwise-idle caller stream.
    // tail2 is the long pole: its weights convert first.
    cvt_on(0, W_tail2, hWt2, (size_t)N_TAIL2 * E2);
    cudaEventRecord(evWt2, 0);
    cvt_on(0, W_tail1, hWt1, (size_t)N_TAIL1 * E1);
    cudaEventRecord(evWt1, 0);

    // chain C first (longest): proj2 -> tail2 (8-warp variants)
    cudaStreamWaitEvent(sC, evRoot, 0);
    cvt_on(sC, W_proj2, hWp2, (size_t)E2 * HIDDEN);
    tc_gemm<0, 8><<<dim3(8, E2 / 128), 256, SMEM_BYTES, sC>>>(
        hx, HIDDEN, hWp2, HIDDEN, E2, HIDDEN, proj2, E2, nullptr);
    cudaStreamWaitEvent(sC, evWt2, 0);
    tc_gemm<2, 8><<<dim3(8, (N_TAIL2 + 127) / 128), 256, SMEM_BYTES, sC>>>(
        proj2, E2, hWt2, E2, N_TAIL2, E2, tl2, N_TAIL2, se2);

    // chain B: proj1 -> tail1 (8-warp variants)
    cudaStreamWaitEvent(sB, evRoot, 0);
    cvt_on(sB, W_proj1, hWp1, (size_t)E1 * HIDDEN);
    tc_gemm<0, 8><<<dim3(8, E1 / 128), 256, SMEM_BYTES, sB>>>(
        hx, HIDDEN, hWp1, HIDDEN, E1, HIDDEN, proj1, E1, nullptr);
    cudaStreamWaitEvent(sB, evWt1, 0);
    tc_gemm<2, 8><<<dim3(8, (N_TAIL1 + 127) / 128), 256, SMEM_BYTES, sB>>>(
        proj1, E1, hWt1, E1, N_TAIL1, E1, tl1, N_TAIL1, se1);

    // chain A: head (4-warp variant, K=1024)
    cudaStreamWaitEvent(sA, evRoot, 0);
    cvt_on(sA, W_head, hWh, (size_t)N_HEAD * HIDDEN);
    tc_gemm<1, 4><<<dim3(8, (N_HEAD + 127) / 128), 128, SMEM_BYTES, sA>>>(
        hx, HIDDEN, hWh, HIDDEN, N_HEAD, HIDDEN, out, OUT_STRIDE, nullptr);
    cudaEventRecord(evHead, sA);

    // fixups (need head's cluster logits + own tail's sumexp/logits)
    cudaStreamWaitEvent(sC, evHead, 0);
    fixup_kernel<<<dim3((N_TAIL2 / 8 + 255) / 256, M_ROWS), 256, 0, sC>>>(
        out, tl2, se2, 60000, N_TAIL2, 1);
    cudaEventRecord(evF2, sC);

    cudaStreamWaitEvent(sB, evHead, 0);
    fixup_kernel<<<dim3((N_TAIL1 / 8 + 255) / 256, M_ROWS), 256, 0, sB>>>(
        out, tl1, se1, 20000, N_TAIL1, 0);
    cudaEventRecord(evF1, sB);

    cudaStreamWaitEvent(0, evF1, 0);
    cudaStreamWaitEvent(0, evF2, 0);

    cudaEventDestroy(evRoot);
    cudaEventDestroy(evHead);
    cudaEventDestroy(evWt1);
    cudaEventDestroy(evWt2);
    cudaEventDestroy(evF1);
    cudaEventDestroy(evF2);
    cudaStreamDestroy(sA);
    cudaStreamDestroy(sB);
    cudaStreamDestroy(sC);
}